// round 9
// baseline (speedup 1.0000x reference)
#include <cuda_runtime.h>
#include <cuda_bf16.h>
#include <math_constants.h>
#include <cstdint>

// Tropical (max-plus) matmul via log-sum-exp + bf16 mma.sync GEMM.
//   y[b,i] = mx_b + T*( ln( sum_j e^{(x_bj-mx_b)/T + CA} * e^{W_ij/T} ) - CA )
// T = 0.005, CA = 20.
//
// R7: fused single kernel, 512 threads/CTA (16 warps/SM both phases):
//   prep (fast exp2) -> replay-safe grid barrier -> 128x64 double-buffered
//   mma.sync GEMM -> fast_ln epilogue staged in smem -> coalesced stores.

#define KDIM 512
#define NDIM 512
#define MAXB 2048
#define T_VAL 0.005f
#define CA_SHIFT 20.0f
#define C1_X 288.539008f   // (1/T)*log2(e)
#define C0_X 28.8539008f   // CA*log2(e)

__device__ float g_mx[MAXB];
__device__ __align__(16) __nv_bfloat16 g_Ax[MAXB * KDIM];
__device__ __align__(16) __nv_bfloat16 g_Bw[NDIM * KDIM];
__device__ unsigned g_arrive = 0;
__device__ unsigned g_phase  = 0;   // monotonic across graph replays

// ---- fast exp2 / ln: FMA pipe only ----
__device__ __forceinline__ float fast_exp2(float t)
{
    t = fminf(fmaxf(t, -125.0f), 125.0f);
    float r = t + 12582912.0f;
    int   iv = __float_as_int(r) - 0x4B400000;
    float f  = t - (r - 12582912.0f);
    float p  = 0.0009618f;
    p = fmaf(p, f, 0.0096181f);
    p = fmaf(p, f, 0.0555041f);
    p = fmaf(p, f, 0.2402265f);
    p = fmaf(p, f, 0.6931472f);
    p = fmaf(p, f, 1.0f);
    return __int_as_float(__float_as_int(p) + (iv << 23));
}

__device__ __forceinline__ float fast_ln(float v)
{
    int   iv = __float_as_int(v);
    float e  = (float)((iv >> 23) - 127);
    float m  = __int_as_float((iv & 0x7FFFFF) | 0x3F800000);
    float p  = -0.0565708f;
    p = fmaf(p, m,  0.4471796f);
    p = fmaf(p, m, -1.4699568f);
    p = fmaf(p, m,  2.8212026f);
    p = fmaf(p, m, -1.7417939f);
    return fmaf(e, 0.6931472f, p);
}

// ---------------- per-row prep (one warp per row) ----------------

__device__ __forceinline__ void prep_row(const float* __restrict__ x,
                                         const float* __restrict__ w,
                                         int gr, int Brows, int lane)
{
    if (gr < Brows) {
        const float4* xr = (const float4*)(x + (size_t)gr * KDIM);
        float4 v[4];
        #pragma unroll
        for (int p = 0; p < 4; p++) v[p] = xr[lane + 32 * p];

        float m = -CUDART_INF_F;
        #pragma unroll
        for (int p = 0; p < 4; p++)
            m = fmaxf(m, fmaxf(fmaxf(v[p].x, v[p].y), fmaxf(v[p].z, v[p].w)));
        #pragma unroll
        for (int o = 16; o; o >>= 1) m = fmaxf(m, __shfl_xor_sync(0xffffffffu, m, o));
        if (lane == 0) g_mx[gr] = m;

        const float base = fmaf(-m, C1_X, C0_X);
        __nv_bfloat162* orow = (__nv_bfloat162*)(g_Ax + (size_t)gr * KDIM);
        #pragma unroll
        for (int p = 0; p < 4; p++) {
            float4 t = v[p];
            float e0 = fast_exp2(fmaf(t.x, C1_X, base));
            float e1 = fast_exp2(fmaf(t.y, C1_X, base));
            float e2 = fast_exp2(fmaf(t.z, C1_X, base));
            float e3 = fast_exp2(fmaf(t.w, C1_X, base));
            orow[(lane + 32 * p) * 2 + 0] = __floats2bfloat162_rn(e0, e1);
            orow[(lane + 32 * p) * 2 + 1] = __floats2bfloat162_rn(e2, e3);
        }
    } else {
        const int row = gr - Brows;
        const float4* wr = (const float4*)(w + (size_t)row * KDIM);
        __nv_bfloat162* orow = (__nv_bfloat162*)(g_Bw + (size_t)row * KDIM);
        #pragma unroll
        for (int p = 0; p < 4; p++) {
            float4 t = wr[lane + 32 * p];
            float e0 = fast_exp2(t.x * C1_X);
            float e1 = fast_exp2(t.y * C1_X);
            float e2 = fast_exp2(t.z * C1_X);
            float e3 = fast_exp2(t.w * C1_X);
            orow[(lane + 32 * p) * 2 + 0] = __floats2bfloat162_rn(e0, e1);
            orow[(lane + 32 * p) * 2 + 1] = __floats2bfloat162_rn(e2, e3);
        }
    }
}

// ---------------- mma helpers ----------------

__device__ __forceinline__ void ldsm_x4(uint32_t& r0, uint32_t& r1,
                                        uint32_t& r2, uint32_t& r3, const void* p)
{
    uint32_t a = (uint32_t)__cvta_generic_to_shared(p);
    asm volatile("ldmatrix.sync.aligned.m8n8.x4.shared.b16 {%0,%1,%2,%3}, [%4];"
                 : "=r"(r0), "=r"(r1), "=r"(r2), "=r"(r3) : "r"(a));
}

__device__ __forceinline__ void mma_bf16(float* c, const uint32_t* a, uint32_t b0, uint32_t b1)
{
    asm volatile(
        "mma.sync.aligned.m16n8k16.row.col.f32.bf16.bf16.f32 "
        "{%0,%1,%2,%3},{%4,%5,%6,%7},{%8,%9},{%0,%1,%2,%3};"
        : "+f"(c[0]), "+f"(c[1]), "+f"(c[2]), "+f"(c[3])
        : "r"(a[0]), "r"(a[1]), "r"(a[2]), "r"(a[3]), "r"(b0), "r"(b1));
}

#define BK 64
#define NKIT (KDIM / BK)   // 8
#define SROW 72            // 144 B row stride: ldmatrix + STS.128 conflict-free

struct Frag { uint32_t a[2][4]; uint32_t b[4]; };

// ---------------- fused kernel ----------------
// grid (8,16) = 128 CTAs x 512 threads; 55 KB smem -> 1 CTA/SM, 16 warps/SM.
// All 128 CTAs co-resident -> grid barrier is safe.

__global__ __launch_bounds__(512)
void fused_kernel(const float* __restrict__ x, const float* __restrict__ W,
                  float* __restrict__ out, int Brows)
{
    __shared__ __align__(16) __nv_bfloat16 As[2][128][SROW];   // 36.9 KB
    __shared__ __align__(16) __nv_bfloat16 Bs[2][64][SROW];    // 18.4 KB

    const int tid  = threadIdx.x;
    const int warp = tid >> 5, lane = tid & 31;
    const int cta  = blockIdx.y * gridDim.x + blockIdx.x;
    const int ncta = gridDim.x * gridDim.y;

    // ---- phase 1: prep, ~1.25 rows per warp across 2048 warps ----
    const int totrows = Brows + NDIM;         // 2560
    const int nwarps  = ncta * 16;            // 2048
    for (int gr = cta * 16 + warp; gr < totrows; gr += nwarps)
        prep_row(x, W, gr, Brows, lane);

    // ---- grid-wide barrier (replay-safe: g_phase monotonic) ----
    __threadfence();
    __syncthreads();
    if (tid == 0) {
        const unsigned my = *(volatile unsigned*)&g_phase;
        const unsigned t  = atomicAdd(&g_arrive, 1);
        if (t == (unsigned)ncta - 1) {
            g_arrive = 0;
            __threadfence();
            atomicAdd(&g_phase, 1);
        } else {
            while (*(volatile unsigned*)&g_phase == my) { }
        }
        __threadfence();
    }
    __syncthreads();

    // ---- phase 2: 128x64 GEMM, 4x4 warp grid, 32x16 warp tiles ----
    const int wm = warp & 3, wn = warp >> 2;
    const int bm = blockIdx.y * 128, bn = blockIdx.x * 64;

    const int arow = tid >> 3;          // 0..63
    const int ac8  = tid & 7;           // 16B chunk
    const int lr   = lane & 15;
    const int lh   = (lane >> 4) * 8;
    const int A_ROWSTEP = 64 * KDIM / 8;   // uint4 stride for +64 rows

    float acc[2][2][4];
    #pragma unroll
    for (int i = 0; i < 2; i++)
        #pragma unroll
        for (int j = 0; j < 2; j++)
            #pragma unroll
            for (int k = 0; k < 4; k++) acc[i][j][k] = 0.f;

    const uint4* ag = (const uint4*)(g_Ax + (size_t)(bm + arow) * KDIM) + ac8;
    const uint4* bg = (const uint4*)(g_Bw + (size_t)(bn + arow) * KDIM) + ac8;

    uint4 pa[2], pb;
    #pragma unroll
    for (int p = 0; p < 2; p++) pa[p] = ag[p * A_ROWSTEP];
    pb = bg[0];
    #pragma unroll
    for (int p = 0; p < 2; p++)
        *(uint4*)&As[0][arow + 64 * p][ac8 * 8] = pa[p];
    *(uint4*)&Bs[0][arow][ac8 * 8] = pb;
    __syncthreads();

    for (int it = 0; it < NKIT; it++) {
        const int cur = it & 1;

        if (it + 1 < NKIT) {
            const int ko = (it + 1) * (BK / 8);
            #pragma unroll
            for (int p = 0; p < 2; p++) pa[p] = ag[ko + p * A_ROWSTEP];
            pb = bg[ko];
        }

        Frag fr[2];
        #pragma unroll
        for (int mt = 0; mt < 2; mt++)
            ldsm_x4(fr[0].a[mt][0], fr[0].a[mt][1], fr[0].a[mt][2], fr[0].a[mt][3],
                    &As[cur][wm * 32 + mt * 16 + lr][lh]);
        ldsm_x4(fr[0].b[0], fr[0].b[1], fr[0].b[2], fr[0].b[3],
                &Bs[cur][wn * 16 + lr][lh]);

        #pragma unroll
        for (int kk = 0; kk < BK / 16; kk++) {
            const int cf = kk & 1, nf = cf ^ 1;
            if (kk + 1 < BK / 16) {
                const int ko = (kk + 1) * 16 + lh;
                #pragma unroll
                for (int mt = 0; mt < 2; mt++)
                    ldsm_x4(fr[nf].a[mt][0], fr[nf].a[mt][1], fr[nf].a[mt][2], fr[nf].a[mt][3],
                            &As[cur][wm * 32 + mt * 16 + lr][ko]);
                ldsm_x4(fr[nf].b[0], fr[nf].b[1], fr[nf].b[2], fr[nf].b[3],
                        &Bs[cur][wn * 16 + lr][ko]);
            }
            #pragma unroll
            for (int mt = 0; mt < 2; mt++) {
                mma_bf16(acc[mt][0], fr[cf].a[mt], fr[cf].b[0], fr[cf].b[2]);
                mma_bf16(acc[mt][1], fr[cf].a[mt], fr[cf].b[1], fr[cf].b[3]);
            }
        }

        if (it + 1 < NKIT) {
            const int nxt = cur ^ 1;
            #pragma unroll
            for (int p = 0; p < 2; p++)
                *(uint4*)&As[nxt][arow + 64 * p][ac8 * 8] = pa[p];
            *(uint4*)&Bs[nxt][arow][ac8 * 8] = pb;
            __syncthreads();
        }
    }

    // ---- epilogue: ln -> smem stage (reuse As) -> coalesced stores ----
    __syncthreads();                       // all smem reads done before aliasing
    float* stg = (float*)&As[0][0][0];     // 128 rows x 68 floats = 34.8 KB

    const int g = lane >> 2, t4 = lane & 3;
    #pragma unroll
    for (int mt = 0; mt < 2; mt++) {
        const int r0 = wm * 32 + mt * 16 + g;
        const float mx0 = __ldg(&g_mx[bm + r0]);
        const float mx1 = __ldg(&g_mx[bm + r0 + 8]);
        #pragma unroll
        for (int nt = 0; nt < 2; nt++) {
            const int c0 = wn * 16 + nt * 8 + 2 * t4;
            stg[r0 * 68 + c0]           = mx0 + T_VAL * (fast_ln(acc[mt][nt][0]) - CA_SHIFT);
            stg[r0 * 68 + c0 + 1]       = mx0 + T_VAL * (fast_ln(acc[mt][nt][1]) - CA_SHIFT);
            stg[(r0 + 8) * 68 + c0]     = mx1 + T_VAL * (fast_ln(acc[mt][nt][2]) - CA_SHIFT);
            stg[(r0 + 8) * 68 + c0 + 1] = mx1 + T_VAL * (fast_ln(acc[mt][nt][3]) - CA_SHIFT);
        }
    }
    __syncthreads();

    #pragma unroll
    for (int s = 0; s < 4; s++) {          // 2048 float4 chunks / 512 threads
        const int i = tid + s * 512;
        const int r = i >> 4, c4 = i & 15;
        float4 v = *(float4*)&stg[r * 68 + c4 * 4];
        *(float4*)&out[(size_t)(bm + r) * NDIM + bn + c4 * 4] = v;
    }
}

// ---------------- launch ----------------

extern "C" void kernel_launch(void* const* d_in, const int* in_sizes, int n_in,
                              void* d_out, int out_size)
{
    const float* x = (const float*)d_in[0];
    const float* W = (const float*)d_in[1];
    int nx = in_sizes[0], nw = in_sizes[1];
    if (nx == NDIM * KDIM && nw != NDIM * KDIM) {   // input-order safety
        const float* t = x; x = W; W = t;
        int ts = nx; nx = nw; nw = ts;
    }
    const int B = nx / KDIM;   // 2048

    dim3 grid(NDIM / 64, B / 128);   // (8,16) = 128 CTAs, all co-resident
    fused_kernel<<<grid, 512>>>(x, W, (float*)d_out, B);
}

// round 10
// speedup vs baseline: 1.2342x; 1.2342x over previous
#include <cuda_runtime.h>
#include <cuda_bf16.h>
#include <math_constants.h>
#include <cstdint>

// Tropical (max-plus) matmul via log-sum-exp + bf16 mma.sync GEMM.
//   y[b,i] = mx_b + T*( ln( sum_j e^{(x_bj-mx_b)/T + CA} * e^{W_ij/T} ) - CA )
// T = 0.005, CA = 20.
//
// R8: ZERO inter-CTA synchronization. Each CTA exp-transforms its OWN
// 128x512 A-tile and 64x512 B-tile directly into smem (redundant across
// CTAs; exp on the MUFU pipe overlaps the L2 reads), then runs a straight
// 32-step full-K ldmatrix+mma mainloop with a single __syncthreads.

#define KDIM 512
#define NDIM 512
#define T_VAL 0.005f
#define CA_SHIFT 20.0f
#define C1_X 288.539008f   // (1/T)*log2(e)
#define C0_X 28.8539008f   // CA*log2(e)

// smem image layout: row stride 520 bf16 = 1040 B (1040/4=260 words ≡ 4 mod 32
// -> ldmatrix 8-row phases hit banks 0,4,...,28: conflict-free, same class as
// the proven SROW=72 layout).
#define RSTR 1040
#define SM_A 0
#define SM_B (128 * RSTR)            // 133120
#define SM_MX (SM_B + 64 * RSTR)     // 199680
#define SMEM_TOTAL (SM_MX + 512)     // 200192 B < 227 KB

__device__ __forceinline__ float ex2_approx(float t)
{
    float r;
    asm("ex2.approx.f32 %0, %1;" : "=f"(r) : "f"(t));
    return r;
}

__device__ __forceinline__ float fast_ln(float v)
{
    // lg2.approx would also work, but keep FMA-pipe ln (MUFU busy elsewhere).
    int   iv = __float_as_int(v);
    float e  = (float)((iv >> 23) - 127);
    float m  = __int_as_float((iv & 0x7FFFFF) | 0x3F800000);
    float p  = -0.0565708f;
    p = fmaf(p, m,  0.4471796f);
    p = fmaf(p, m, -1.4699568f);
    p = fmaf(p, m,  2.8212026f);
    p = fmaf(p, m, -1.7417939f);
    return fmaf(e, 0.6931472f, p);
}

__device__ __forceinline__ void ldsm_x4(uint32_t& r0, uint32_t& r1,
                                        uint32_t& r2, uint32_t& r3, uint32_t a)
{
    asm volatile("ldmatrix.sync.aligned.m8n8.x4.shared.b16 {%0,%1,%2,%3}, [%4];"
                 : "=r"(r0), "=r"(r1), "=r"(r2), "=r"(r3) : "r"(a));
}

__device__ __forceinline__ void mma_bf16(float* c, const uint32_t* a, uint32_t b0, uint32_t b1)
{
    asm volatile(
        "mma.sync.aligned.m16n8k16.row.col.f32.bf16.bf16.f32 "
        "{%0,%1,%2,%3},{%4,%5,%6,%7},{%8,%9},{%0,%1,%2,%3};"
        : "+f"(c[0]), "+f"(c[1]), "+f"(c[2]), "+f"(c[3])
        : "r"(a[0]), "r"(a[1]), "r"(a[2]), "r"(a[3]), "r"(b0), "r"(b1));
}

// ---------------- fused kernel, grid (8,16) x 512 threads ----------------

__global__ __launch_bounds__(512)
void tropical_kernel(const float* __restrict__ x, const float* __restrict__ W,
                     float* __restrict__ out)
{
    extern __shared__ __align__(16) unsigned char smem[];
    float* smx = (float*)(smem + SM_MX);

    const int tid  = threadIdx.x;
    const int warp = tid >> 5, lane = tid & 31;
    const int bm   = blockIdx.y * 128, bn = blockIdx.x * 64;

    // ---- phase 1: prep this CTA's tiles straight into smem ----
    // 192 rows (128 A + 64 B), 12 per warp. MUFU ex2 overlaps the L2 reads.
    #pragma unroll 2
    for (int i = 0; i < 12; i++) {
        const int vr = warp + 16 * i;
        if (vr < 128) {
            const float4* xr = (const float4*)(x + (size_t)(bm + vr) * KDIM);
            float4 v[4];
            #pragma unroll
            for (int p = 0; p < 4; p++) v[p] = xr[lane + 32 * p];

            float m = -CUDART_INF_F;
            #pragma unroll
            for (int p = 0; p < 4; p++)
                m = fmaxf(m, fmaxf(fmaxf(v[p].x, v[p].y), fmaxf(v[p].z, v[p].w)));
            #pragma unroll
            for (int o = 16; o; o >>= 1) m = fmaxf(m, __shfl_xor_sync(0xffffffffu, m, o));
            if (lane == 0) smx[vr] = m;

            const float base = fmaf(-m, C1_X, C0_X);
            __nv_bfloat162* orow = (__nv_bfloat162*)(smem + SM_A + vr * RSTR);
            #pragma unroll
            for (int p = 0; p < 4; p++) {
                float4 t = v[p];
                float e0 = ex2_approx(fmaf(t.x, C1_X, base));
                float e1 = ex2_approx(fmaf(t.y, C1_X, base));
                float e2 = ex2_approx(fmaf(t.z, C1_X, base));
                float e3 = ex2_approx(fmaf(t.w, C1_X, base));
                orow[(lane + 32 * p) * 2 + 0] = __floats2bfloat162_rn(e0, e1);
                orow[(lane + 32 * p) * 2 + 1] = __floats2bfloat162_rn(e2, e3);
            }
        } else {
            const int r = vr - 128;
            const float4* wr = (const float4*)(W + (size_t)(bn + r) * KDIM);
            __nv_bfloat162* orow = (__nv_bfloat162*)(smem + SM_B + r * RSTR);
            #pragma unroll
            for (int p = 0; p < 4; p++) {
                float4 t = wr[lane + 32 * p];
                float e0 = ex2_approx(t.x * C1_X);
                float e1 = ex2_approx(t.y * C1_X);
                float e2 = ex2_approx(t.z * C1_X);
                float e3 = ex2_approx(t.w * C1_X);
                orow[(lane + 32 * p) * 2 + 0] = __floats2bfloat162_rn(e0, e1);
                orow[(lane + 32 * p) * 2 + 1] = __floats2bfloat162_rn(e2, e3);
            }
        }
    }
    __syncthreads();   // the ONLY pre-GEMM sync

    // ---- phase 2: full-K mainloop, 32 k16 steps, no barriers ----
    const int wm = warp & 3, wn = warp >> 2;     // 4x4 warps, 32x16 warp tile
    const int lr = lane & 15;
    const int lh = (lane >> 4) * 8;

    uint32_t aaddr[2], baddr;
    #pragma unroll
    for (int mt = 0; mt < 2; mt++)
        aaddr[mt] = (uint32_t)__cvta_generic_to_shared(
            smem + SM_A + (wm * 32 + mt * 16 + lr) * RSTR + lh * 2);
    baddr = (uint32_t)__cvta_generic_to_shared(
        smem + SM_B + (wn * 16 + lr) * RSTR + lh * 2);

    float acc[2][2][4];
    #pragma unroll
    for (int i = 0; i < 2; i++)
        #pragma unroll
        for (int j = 0; j < 2; j++)
            #pragma unroll
            for (int k = 0; k < 4; k++) acc[i][j][k] = 0.f;

    uint32_t fa[2][2][4], fb[2][4];
    #pragma unroll
    for (int mt = 0; mt < 2; mt++)
        ldsm_x4(fa[0][mt][0], fa[0][mt][1], fa[0][mt][2], fa[0][mt][3], aaddr[mt]);
    ldsm_x4(fb[0][0], fb[0][1], fb[0][2], fb[0][3], baddr);

    #pragma unroll 4
    for (int kk = 0; kk < 32; kk++) {
        const int cf = kk & 1, nf = cf ^ 1;
        if (kk + 1 < 32) {
            const uint32_t off = (uint32_t)(kk + 1) * 32u;   // +16 cols = 32 B
            #pragma unroll
            for (int mt = 0; mt < 2; mt++)
                ldsm_x4(fa[nf][mt][0], fa[nf][mt][1], fa[nf][mt][2], fa[nf][mt][3],
                        aaddr[mt] + off);
            ldsm_x4(fb[nf][0], fb[nf][1], fb[nf][2], fb[nf][3], baddr + off);
        }
        #pragma unroll
        for (int mt = 0; mt < 2; mt++) {
            mma_bf16(acc[mt][0], fa[cf][mt], fb[cf][0], fb[cf][2]);
            mma_bf16(acc[mt][1], fa[cf][mt], fb[cf][1], fb[cf][3]);
        }
    }

    // ---- epilogue: ln -> smem stage (reuse A image) -> coalesced stores ----
    const int g = lane >> 2, t4 = lane & 3;
    float mx0[2], mx1[2];
    #pragma unroll
    for (int mt = 0; mt < 2; mt++) {
        mx0[mt] = smx[wm * 32 + mt * 16 + g];
        mx1[mt] = smx[wm * 32 + mt * 16 + g + 8];
    }
    __syncthreads();                       // all smem reads done before aliasing
    float* stg = (float*)smem;             // 128 rows x 68 floats = 34.8 KB

    #pragma unroll
    for (int mt = 0; mt < 2; mt++) {
        const int r0 = wm * 32 + mt * 16 + g;
        #pragma unroll
        for (int nt = 0; nt < 2; nt++) {
            const int c0 = wn * 16 + nt * 8 + 2 * t4;
            stg[r0 * 68 + c0]           = mx0[mt] + T_VAL * (fast_ln(acc[mt][nt][0]) - CA_SHIFT);
            stg[r0 * 68 + c0 + 1]       = mx0[mt] + T_VAL * (fast_ln(acc[mt][nt][1]) - CA_SHIFT);
            stg[(r0 + 8) * 68 + c0]     = mx1[mt] + T_VAL * (fast_ln(acc[mt][nt][2]) - CA_SHIFT);
            stg[(r0 + 8) * 68 + c0 + 1] = mx1[mt] + T_VAL * (fast_ln(acc[mt][nt][3]) - CA_SHIFT);
        }
    }
    __syncthreads();

    #pragma unroll
    for (int s = 0; s < 4; s++) {          // 2048 float4 chunks / 512 threads
        const int i = tid + s * 512;
        const int r = i >> 4, c4 = i & 15;
        float4 v = *(float4*)&stg[r * 68 + c4 * 4];
        *(float4*)&out[(size_t)(bm + r) * NDIM + bn + c4 * 4] = v;
    }
}

// ---------------- launch ----------------

extern "C" void kernel_launch(void* const* d_in, const int* in_sizes, int n_in,
                              void* d_out, int out_size)
{
    const float* x = (const float*)d_in[0];
    const float* W = (const float*)d_in[1];
    int nx = in_sizes[0], nw = in_sizes[1];
    if (nx == NDIM * KDIM && nw != NDIM * KDIM) {   // input-order safety
        const float* t = x; x = W; W = t;
        int ts = nx; nx = nw; nw = ts;
    }
    const int B = nx / KDIM;   // 2048

    cudaFuncSetAttribute(tropical_kernel,
                         cudaFuncAttributeMaxDynamicSharedMemorySize, SMEM_TOTAL);
    dim3 grid(NDIM / 64, B / 128);   // (8,16) = 128 CTAs
    tropical_kernel<<<grid, 512, SMEM_TOTAL>>>(x, W, (float*)d_out);
}